// round 5
// baseline (speedup 1.0000x reference)
#include <cuda_runtime.h>
#include <cuda_bf16.h>
#include <cstdint>

// Problem constants (fixed by dataset; runtime values read from in_sizes).
#define NMAX 50000
#define EMAX 600000

// ---------------- scratch (device globals; no allocation allowed) ----------
__device__ int   g_cnt[NMAX];
__device__ int   g_rowptr[NMAX + 1];
__device__ int   g_wptr[NMAX];
__device__ int   g_esrc[EMAX];
__device__ float g_ecoef[EMAX];   // dinv[src] per (dst-sorted) edge
__device__ float g_dinv[NMAX];
__device__ float g_H[(size_t)NMAX * 128];   // GEMM output h = In @ W
__device__ float g_A[(size_t)NMAX * 128];   // layer activations
__device__ int   g_bsums[128];              // scan block sums (49 used)

// ---------------- CSR build ------------------------------------------------
__global__ void k_zero_cnt(int n) {
    int i = blockIdx.x * blockDim.x + threadIdx.x;
    if (i < n) g_cnt[i] = 0;
}

__global__ void k_count(const int* __restrict__ dst, int e) {
    int i = blockIdx.x * blockDim.x + threadIdx.x;
    if (i < e) atomicAdd(&g_cnt[dst[i]], 1);
}

__global__ void k_dinv(int n) {
    int i = blockIdx.x * blockDim.x + threadIdx.x;
    if (i < n) g_dinv[i] = rsqrtf((float)g_cnt[i] + 1.0f);  // +1 self loop
}

// Block-level inclusive scan (Hillis-Steele) -> exclusive per-element,
// block totals to g_bsums.
__global__ void k_scan_block(int n) {
    __shared__ int sh[1024];
    int i = blockIdx.x * 1024 + threadIdx.x;
    int v = (i < n) ? g_cnt[i] : 0;
    sh[threadIdx.x] = v;
    __syncthreads();
    for (int off = 1; off < 1024; off <<= 1) {
        int t = (threadIdx.x >= off) ? sh[threadIdx.x - off] : 0;
        __syncthreads();
        sh[threadIdx.x] += t;
        __syncthreads();
    }
    if (i < n) g_rowptr[i] = sh[threadIdx.x] - v;  // exclusive
    if (threadIdx.x == 1023) g_bsums[blockIdx.x] = sh[1023];
}

__global__ void k_scan_tops(int nb, int n) {
    if (threadIdx.x == 0 && blockIdx.x == 0) {
        int run = 0;
        for (int b = 0; b < nb; b++) {
            int t = g_bsums[b];
            g_bsums[b] = run;
            run += t;
        }
        g_rowptr[n] = run;  // == e
    }
}

__global__ void k_scan_add(int n) {
    int i = blockIdx.x * blockDim.x + threadIdx.x;
    if (i < n) {
        int v = g_rowptr[i] + g_bsums[i >> 10];
        g_rowptr[i] = v;
        g_wptr[i]   = v;
    }
}

__global__ void k_fill(const int* __restrict__ src, const int* __restrict__ dst, int e) {
    int i = blockIdx.x * blockDim.x + threadIdx.x;
    if (i < e) {
        int s = src[i];
        int d = dst[i];
        int idx = atomicAdd(&g_wptr[d], 1);
        g_esrc[idx]  = s;
        g_ecoef[idx] = g_dinv[s];
    }
}

// ---------------- GEMM: Out[n,M] = In[n,K] @ W[K,M] ------------------------
template <int K, int M>
__global__ __launch_bounds__(256)
void gemm_kernel(const float* __restrict__ In, const float* __restrict__ W,
                 float* __restrict__ Out, int n) {
    constexpr int BM = 64;
    constexpr int BK = 16;
    constexpr int CT = (M >= 128) ? 4 : (M >= 64) ? 2 : 1;  // cols per thread

    __shared__ float In_s[BM][K];
    __shared__ float Ws[BK][M];

    const int tid  = threadIdx.x;
    const int row0 = blockIdx.x * BM;

    // Load input tile (vectorized, zero-padded past n)
    constexpr int K4 = K / 4;
    for (int idx = tid; idx < BM * K4; idx += 256) {
        int r = idx / K4, c = idx % K4;
        int gr = row0 + r;
        float4 v = make_float4(0.f, 0.f, 0.f, 0.f);
        if (gr < n) v = *(const float4*)(In + (size_t)gr * K + c * 4);
        *(float4*)&In_s[r][c * 4] = v;
    }

    const int warp = tid >> 5, lane = tid & 31;
    const int r0 = warp * 8;
    const int c0 = lane * CT;

    float acc[8][CT];
#pragma unroll
    for (int i = 0; i < 8; i++)
#pragma unroll
        for (int t = 0; t < CT; t++) acc[i][t] = 0.f;

    for (int kk = 0; kk < K; kk += BK) {
        __syncthreads();  // also covers In_s on first iteration
        for (int idx = tid; idx < BK * M; idx += 256) {
            int k = idx / M, c = idx % M;
            Ws[k][c] = W[(size_t)(kk + k) * M + c];
        }
        __syncthreads();
#pragma unroll
        for (int k = 0; k < BK; k++) {
            float w[CT];
            if constexpr (CT == 4) {
                float4 wv = *(const float4*)&Ws[k][c0];
                w[0] = wv.x; w[1] = wv.y; w[2] = wv.z; w[3] = wv.w;
            } else if constexpr (CT == 2) {
                float2 wv = *(const float2*)&Ws[k][c0];
                w[0] = wv.x; w[1] = wv.y;
            } else {
                w[0] = (c0 < M) ? Ws[k][c0] : 0.f;
            }
#pragma unroll
            for (int i = 0; i < 8; i++) {
                float a = In_s[r0 + i][kk + k];
#pragma unroll
                for (int t = 0; t < CT; t++) acc[i][t] += a * w[t];
            }
        }
    }

#pragma unroll
    for (int i = 0; i < 8; i++) {
        int gr = row0 + r0 + i;
        if (gr < n) {
            if constexpr (CT == 4) {
                *(float4*)(Out + (size_t)gr * M + c0) =
                    make_float4(acc[i][0], acc[i][1], acc[i][2], acc[i][3]);
            } else if constexpr (CT == 2) {
                *(float2*)(Out + (size_t)gr * M + c0) =
                    make_float2(acc[i][0], acc[i][1]);
            } else {
                if (c0 < M) Out[(size_t)gr * M + c0] = acc[i][0];
            }
        }
    }
}

// ---------------- Aggregation (gather-based segment sum) -------------------
// One warp (or 32/M nodes per warp if M<32) per dst node:
//   out[d] = sum_{e: dst=d} h[src_e] * dinv[src_e]*dinv[d]  +  h[d]*dinv[d]^2 + b
template <int M, bool RELU>
__global__ __launch_bounds__(256)
void agg_kernel(const float* __restrict__ H, const float* __restrict__ bias,
                float* __restrict__ Out, int n) {
    constexpr int NPW = (M >= 32) ? 1 : (32 / M);
    constexpr int CT  = (M >= 128) ? 4 : (M >= 64) ? 2 : 1;

    int gwarp = (blockIdx.x * blockDim.x + threadIdx.x) >> 5;
    int lane  = threadIdx.x & 31;

    int d, c0;
    if constexpr (NPW == 1) {
        d  = gwarp;
        c0 = lane * CT;
    } else {
        d  = gwarp * NPW + lane / M;
        c0 = lane % M;
    }
    if (d >= n) return;

    float dd   = g_dinv[d];
    float self = dd * dd;

    float acc[CT];
    {
        const float* hd = H + (size_t)d * M + c0;
        if constexpr (CT == 4) {
            float4 hv = *(const float4*)hd;
            float4 bv = *(const float4*)(bias + c0);
            acc[0] = hv.x * self + bv.x;
            acc[1] = hv.y * self + bv.y;
            acc[2] = hv.z * self + bv.z;
            acc[3] = hv.w * self + bv.w;
        } else if constexpr (CT == 2) {
            float2 hv = *(const float2*)hd;
            float2 bv = *(const float2*)(bias + c0);
            acc[0] = hv.x * self + bv.x;
            acc[1] = hv.y * self + bv.y;
        } else {
            acc[0] = hd[0] * self + bias[c0];
        }
    }

    int jb = g_rowptr[d], je = g_rowptr[d + 1];
    for (int j = jb; j < je; j++) {
        int   s  = g_esrc[j];
        float cf = dd * g_ecoef[j];
        const float* hs = H + (size_t)s * M + c0;
        if constexpr (CT == 4) {
            float4 v = *(const float4*)hs;
            acc[0] += v.x * cf;
            acc[1] += v.y * cf;
            acc[2] += v.z * cf;
            acc[3] += v.w * cf;
        } else if constexpr (CT == 2) {
            float2 v = *(const float2*)hs;
            acc[0] += v.x * cf;
            acc[1] += v.y * cf;
        } else {
            acc[0] += hs[0] * cf;
        }
    }

    if constexpr (RELU) {
#pragma unroll
        for (int t = 0; t < CT; t++) acc[t] = fmaxf(acc[t], 0.f);
    }

    float* od = Out + (size_t)d * M + c0;
    if constexpr (CT == 4) {
        *(float4*)od = make_float4(acc[0], acc[1], acc[2], acc[3]);
    } else if constexpr (CT == 2) {
        *(float2*)od = make_float2(acc[0], acc[1]);
    } else {
        od[0] = acc[0];
    }
}

// ---------------- launcher -------------------------------------------------
extern "C" void kernel_launch(void* const* d_in, const int* in_sizes, int n_in,
                              void* d_out, int out_size) {
    const float* x  = (const float*)d_in[0];
    const int*   ei = (const int*)d_in[1];   // [2, E] int32
    const float* W1 = (const float*)d_in[2];
    const float* b1 = (const float*)d_in[3];
    const float* W2 = (const float*)d_in[4];
    const float* b2 = (const float*)d_in[5];
    const float* W3 = (const float*)d_in[6];
    const float* b3 = (const float*)d_in[7];

    const int n = in_sizes[0] / 128;
    const int e = in_sizes[1] / 2;
    const int* src = ei;
    const int* dst = ei + e;

    void *pH = nullptr, *pA = nullptr;
    cudaGetSymbolAddress(&pH, g_H);
    cudaGetSymbolAddress(&pA, g_A);
    float* H = (float*)pH;
    float* A = (float*)pA;
    float* out = (float*)d_out;

    const int TB = 256;
    const int gn = (n + TB - 1) / TB;
    const int ge = (e + TB - 1) / TB;

    // CSR build (shared by all 3 layers)
    k_zero_cnt<<<gn, TB>>>(n);
    k_count<<<ge, TB>>>(dst, e);
    k_dinv<<<gn, TB>>>(n);
    int nb = (n + 1023) / 1024;
    k_scan_block<<<nb, 1024>>>(n);
    k_scan_tops<<<1, 32>>>(nb, n);
    k_scan_add<<<gn, TB>>>(n);
    k_fill<<<ge, TB>>>(src, dst, e);

    // Layer 1: 128 -> 128, ReLU
    gemm_kernel<128, 128><<<(n + 63) / 64, 256>>>(x, W1, H, n);
    agg_kernel<128, true><<<(n + 7) / 8, 256>>>(H, b1, A, n);

    // Layer 2: 128 -> 64, ReLU
    gemm_kernel<128, 64><<<(n + 63) / 64, 256>>>(A, W2, H, n);
    agg_kernel<64, true><<<(n + 7) / 8, 256>>>(H, b2, A, n);

    // Layer 3: 64 -> 16
    gemm_kernel<64, 16><<<(n + 63) / 64, 256>>>(A, W3, H, n);
    {
        const int NPW = 2;  // 16-wide rows, 2 nodes per warp
        int warps  = (n + NPW - 1) / NPW;
        int blocks = (warps * 32 + 255) / 256;
        agg_kernel<16, false><<<blocks, 256>>>(H, b3, out, n);
    }
}

// round 6
// speedup vs baseline: 1.0399x; 1.0399x over previous
#include <cuda_runtime.h>
#include <cuda_bf16.h>
#include <cstdint>

// Problem constants (fixed by dataset; runtime values read from in_sizes).
#define NMAX 50000
#define EMAX 600000

// ---------------- scratch (device globals; no allocation allowed) ----------
// NOTE: g_cnt is zero at module load and is re-zeroed by k_scan_add at the end
// of every launch, so each launch (and each graph replay) starts from the same
// state -> deterministic.
__device__ int   g_cnt[NMAX];
__device__ int   g_rowptr[NMAX + 1];
__device__ int   g_wptr[NMAX];
__device__ int   g_esrc[EMAX];
__device__ float g_dinv[NMAX];
__device__ float g_H[(size_t)NMAX * 128];   // GEMM output, pre-scaled by dinv[row]
__device__ float g_A[(size_t)NMAX * 128];   // layer activations
__device__ int   g_bsums[128];              // scan block sums (49 used)

// ---------------- CSR build ------------------------------------------------
__global__ void k_count(const int* __restrict__ dst, int e) {
    int i = blockIdx.x * blockDim.x + threadIdx.x;
    if (i < e) atomicAdd(&g_cnt[dst[i]], 1);
}

// Block-level inclusive scan -> exclusive per-element, block totals to
// g_bsums. Also computes dinv (counts already in hand).
__global__ void k_scan_block(int n) {
    __shared__ int sh[1024];
    int i = blockIdx.x * 1024 + threadIdx.x;
    int v = (i < n) ? g_cnt[i] : 0;
    sh[threadIdx.x] = v;
    __syncthreads();
    for (int off = 1; off < 1024; off <<= 1) {
        int t = (threadIdx.x >= off) ? sh[threadIdx.x - off] : 0;
        __syncthreads();
        sh[threadIdx.x] += t;
        __syncthreads();
    }
    if (i < n) {
        g_rowptr[i] = sh[threadIdx.x] - v;             // exclusive
        g_dinv[i]   = rsqrtf((float)v + 1.0f);         // +1 self loop
    }
    if (threadIdx.x == 1023) g_bsums[blockIdx.x] = sh[1023];
}

// 64-wide parallel scan of the (<=64) block totals.
__global__ void k_scan_tops(int nb, int n) {
    __shared__ int sh[64];
    int t = threadIdx.x;
    int v = (t < nb) ? g_bsums[t] : 0;
    sh[t] = v;
    __syncthreads();
    for (int off = 1; off < 64; off <<= 1) {
        int u = (t >= off) ? sh[t - off] : 0;
        __syncthreads();
        sh[t] += u;
        __syncthreads();
    }
    if (t < nb) g_bsums[t] = sh[t] - v;   // exclusive
    if (t == 63) g_rowptr[n] = sh[63];    // == e
}

__global__ void k_scan_add(int n) {
    int i = blockIdx.x * blockDim.x + threadIdx.x;
    if (i < n) {
        int v = g_rowptr[i] + g_bsums[i >> 10];
        g_rowptr[i] = v;
        g_wptr[i]   = v;
        g_cnt[i]    = 0;   // reset for the next launch (deterministic state)
    }
}

__global__ void k_fill(const int* __restrict__ src, const int* __restrict__ dst, int e) {
    int i = blockIdx.x * blockDim.x + threadIdx.x;
    if (i < e) {
        int s = src[i];
        int d = dst[i];
        int idx = atomicAdd(&g_wptr[d], 1);
        g_esrc[idx] = s;
    }
}

// ---------------- GEMM: Out[n,M] = (In[n,K] @ W[K,M]) * dinv[row] ----------
template <int K, int M>
__global__ __launch_bounds__(256)
void gemm_kernel(const float* __restrict__ In, const float* __restrict__ W,
                 float* __restrict__ Out, int n) {
    constexpr int BM = 64;
    constexpr int BK = 16;
    constexpr int CT = (M >= 128) ? 4 : (M >= 64) ? 2 : 1;  // cols per thread

    __shared__ float In_s[BM][K];
    __shared__ float Ws[BK][M];

    const int tid  = threadIdx.x;
    const int row0 = blockIdx.x * BM;

    // Load input tile (vectorized, zero-padded past n)
    constexpr int K4 = K / 4;
    for (int idx = tid; idx < BM * K4; idx += 256) {
        int r = idx / K4, c = idx % K4;
        int gr = row0 + r;
        float4 v = make_float4(0.f, 0.f, 0.f, 0.f);
        if (gr < n) v = *(const float4*)(In + (size_t)gr * K + c * 4);
        *(float4*)&In_s[r][c * 4] = v;
    }

    const int warp = tid >> 5, lane = tid & 31;
    const int r0 = warp * 8;
    const int c0 = lane * CT;

    float acc[8][CT];
#pragma unroll
    for (int i = 0; i < 8; i++)
#pragma unroll
        for (int t = 0; t < CT; t++) acc[i][t] = 0.f;

    for (int kk = 0; kk < K; kk += BK) {
        __syncthreads();  // also covers In_s on first iteration
        for (int idx = tid; idx < BK * M; idx += 256) {
            int k = idx / M, c = idx % M;
            Ws[k][c] = W[(size_t)(kk + k) * M + c];
        }
        __syncthreads();
#pragma unroll
        for (int k = 0; k < BK; k++) {
            float w[CT];
            if constexpr (CT == 4) {
                float4 wv = *(const float4*)&Ws[k][c0];
                w[0] = wv.x; w[1] = wv.y; w[2] = wv.z; w[3] = wv.w;
            } else if constexpr (CT == 2) {
                float2 wv = *(const float2*)&Ws[k][c0];
                w[0] = wv.x; w[1] = wv.y;
            } else {
                w[0] = (c0 < M) ? Ws[k][c0] : 0.f;
            }
#pragma unroll
            for (int i = 0; i < 8; i++) {
                float a = In_s[r0 + i][kk + k];
#pragma unroll
                for (int t = 0; t < CT; t++) acc[i][t] += a * w[t];
            }
        }
    }

#pragma unroll
    for (int i = 0; i < 8; i++) {
        int gr = row0 + r0 + i;
        if (gr < n) {
            float sc = g_dinv[gr];  // pre-scale row: H' = h * dinv[row]
            if constexpr (CT == 4) {
                *(float4*)(Out + (size_t)gr * M + c0) =
                    make_float4(acc[i][0] * sc, acc[i][1] * sc,
                                acc[i][2] * sc, acc[i][3] * sc);
            } else if constexpr (CT == 2) {
                *(float2*)(Out + (size_t)gr * M + c0) =
                    make_float2(acc[i][0] * sc, acc[i][1] * sc);
            } else {
                if (c0 < M) Out[(size_t)gr * M + c0] = acc[i][0] * sc;
            }
        }
    }
}

// ---------------- Aggregation (gather-based segment sum) -------------------
// H is pre-scaled: H'[i] = h[i] * dinv[i]. Then
//   out[d] = dinv[d] * ( sum_{e: dst=d} H'[src_e] + H'[d] ) + b
template <int M, bool RELU>
__global__ __launch_bounds__(256)
void agg_kernel(const float* __restrict__ H, const float* __restrict__ bias,
                float* __restrict__ Out, int n) {
    constexpr int NPW = (M >= 32) ? 1 : (32 / M);
    constexpr int CT  = (M >= 128) ? 4 : (M >= 64) ? 2 : 1;

    int gwarp = (blockIdx.x * blockDim.x + threadIdx.x) >> 5;
    int lane  = threadIdx.x & 31;

    int d, c0;
    if constexpr (NPW == 1) {
        d  = gwarp;
        c0 = lane * CT;
    } else {
        d  = gwarp * NPW + lane / M;
        c0 = lane % M;
    }
    if (d >= n) return;

    float dd = g_dinv[d];

    float acc[CT];
    {
        const float* hd = H + (size_t)d * M + c0;  // self loop: + H'[d]
        if constexpr (CT == 4) {
            float4 hv = *(const float4*)hd;
            acc[0] = hv.x; acc[1] = hv.y; acc[2] = hv.z; acc[3] = hv.w;
        } else if constexpr (CT == 2) {
            float2 hv = *(const float2*)hd;
            acc[0] = hv.x; acc[1] = hv.y;
        } else {
            acc[0] = hd[0];
        }
    }

    const int jb = g_rowptr[d], je = g_rowptr[d + 1];
    int j = jb;
    // 4-way unrolled gather: 4 independent row loads in flight per warp.
    for (; j + 4 <= je; j += 4) {
        int s0 = g_esrc[j + 0];
        int s1 = g_esrc[j + 1];
        int s2 = g_esrc[j + 2];
        int s3 = g_esrc[j + 3];
        const float* h0 = H + (size_t)s0 * M + c0;
        const float* h1 = H + (size_t)s1 * M + c0;
        const float* h2 = H + (size_t)s2 * M + c0;
        const float* h3 = H + (size_t)s3 * M + c0;
        if constexpr (CT == 4) {
            float4 v0 = *(const float4*)h0;
            float4 v1 = *(const float4*)h1;
            float4 v2 = *(const float4*)h2;
            float4 v3 = *(const float4*)h3;
            acc[0] += (v0.x + v1.x) + (v2.x + v3.x);
            acc[1] += (v0.y + v1.y) + (v2.y + v3.y);
            acc[2] += (v0.z + v1.z) + (v2.z + v3.z);
            acc[3] += (v0.w + v1.w) + (v2.w + v3.w);
        } else if constexpr (CT == 2) {
            float2 v0 = *(const float2*)h0;
            float2 v1 = *(const float2*)h1;
            float2 v2 = *(const float2*)h2;
            float2 v3 = *(const float2*)h3;
            acc[0] += (v0.x + v1.x) + (v2.x + v3.x);
            acc[1] += (v0.y + v1.y) + (v2.y + v3.y);
        } else {
            float v0 = h0[0], v1 = h1[0], v2 = h2[0], v3 = h3[0];
            acc[0] += (v0 + v1) + (v2 + v3);
        }
    }
    for (; j < je; j++) {
        int s = g_esrc[j];
        const float* hs = H + (size_t)s * M + c0;
        if constexpr (CT == 4) {
            float4 v = *(const float4*)hs;
            acc[0] += v.x; acc[1] += v.y; acc[2] += v.z; acc[3] += v.w;
        } else if constexpr (CT == 2) {
            float2 v = *(const float2*)hs;
            acc[0] += v.x; acc[1] += v.y;
        } else {
            acc[0] += hs[0];
        }
    }

    // final: out = dd*acc + bias  (+ relu)
#pragma unroll
    for (int t = 0; t < CT; t++) {
        float r = acc[t] * dd + bias[c0 + t];
        acc[t] = RELU ? fmaxf(r, 0.f) : r;
    }

    float* od = Out + (size_t)d * M + c0;
    if constexpr (CT == 4) {
        *(float4*)od = make_float4(acc[0], acc[1], acc[2], acc[3]);
    } else if constexpr (CT == 2) {
        *(float2*)od = make_float2(acc[0], acc[1]);
    } else {
        od[0] = acc[0];
    }
}

// ---------------- launcher -------------------------------------------------
extern "C" void kernel_launch(void* const* d_in, const int* in_sizes, int n_in,
                              void* d_out, int out_size) {
    const float* x  = (const float*)d_in[0];
    const int*   ei = (const int*)d_in[1];   // [2, E] int32
    const float* W1 = (const float*)d_in[2];
    const float* b1 = (const float*)d_in[3];
    const float* W2 = (const float*)d_in[4];
    const float* b2 = (const float*)d_in[5];
    const float* W3 = (const float*)d_in[6];
    const float* b3 = (const float*)d_in[7];

    const int n = in_sizes[0] / 128;
    const int e = in_sizes[1] / 2;
    const int* src = ei;
    const int* dst = ei + e;

    void *pH = nullptr, *pA = nullptr;
    cudaGetSymbolAddress(&pH, g_H);
    cudaGetSymbolAddress(&pA, g_A);
    float* H = (float*)pH;
    float* A = (float*)pA;
    float* out = (float*)d_out;

    const int TB = 256;
    const int gn = (n + TB - 1) / TB;
    const int ge = (e + TB - 1) / TB;

    // CSR build (shared by all 3 layers). g_cnt starts zero (module init /
    // re-zeroed by k_scan_add at the end of the previous launch).
    k_count<<<ge, TB>>>(dst, e);
    int nb = (n + 1023) / 1024;
    k_scan_block<<<nb, 1024>>>(n);       // also computes g_dinv
    k_scan_tops<<<1, 64>>>(nb, n);
    k_scan_add<<<gn, TB>>>(n);           // also re-zeroes g_cnt
    k_fill<<<ge, TB>>>(src, dst, e);

    // Layer 1: 128 -> 128, ReLU
    gemm_kernel<128, 128><<<(n + 63) / 64, 256>>>(x, W1, H, n);
    agg_kernel<128, true><<<(n + 7) / 8, 256>>>(H, b1, A, n);

    // Layer 2: 128 -> 64, ReLU
    gemm_kernel<128, 64><<<(n + 63) / 64, 256>>>(A, W2, H, n);
    agg_kernel<64, true><<<(n + 7) / 8, 256>>>(H, b2, A, n);

    // Layer 3: 64 -> 16
    gemm_kernel<64, 16><<<(n + 63) / 64, 256>>>(A, W3, H, n);
    {
        const int NPW = 2;  // 16-wide rows, 2 nodes per warp
        int warps  = (n + NPW - 1) / NPW;
        int blocks = (warps * 32 + 255) / 256;
        agg_kernel<16, false><<<blocks, 256>>>(H, b3, out, n);
    }
}